// round 2
// baseline (speedup 1.0000x reference)
#include <cuda_runtime.h>

// Problem constants
#define B_    8
#define N_    1024
#define INF_  128
#define OUTF_ 128
#define H_    4
#define HD_   32
#define NEG   0.2f

// Scratch (no cudaMalloc allowed -> __device__ globals)
__device__ float gH[B_ * N_ * OUTF_];            // projected features, 4 MB
__device__ float gPV[B_ * H_ * 2 * N_ * HD_];    // vector prefix sums, 8.39 MB

// ---------------------------------------------------------------------------
// Kernel 1: h = x @ W   (8192x128 @ 128x128, fp32)
// 64x64 tile, 256 threads, 4x4 register tile, K-loop in chunks of 16.
// ---------------------------------------------------------------------------
__global__ __launch_bounds__(256) void gemm_kernel(const float* __restrict__ A,
                                                   const float* __restrict__ W) {
    __shared__ float As[16][64];
    __shared__ float Bs[16][64];
    const int bm  = blockIdx.x * 64;
    const int bn  = blockIdx.y * 64;
    const int tid = threadIdx.x;
    const int tr  = tid >> 4;   // 0..15
    const int tc  = tid & 15;   // 0..15

    float acc[4][4];
#pragma unroll
    for (int i = 0; i < 4; i++)
#pragma unroll
        for (int j = 0; j < 4; j++) acc[i][j] = 0.f;

    for (int k0 = 0; k0 < 128; k0 += 16) {
#pragma unroll 4
        for (int i = tid; i < 1024; i += 256) {
            int m = i >> 4, kk = i & 15;
            As[kk][m] = A[(bm + m) * 128 + k0 + kk];
        }
#pragma unroll 4
        for (int i = tid; i < 1024; i += 256) {
            int kk = i >> 6, n = i & 63;
            Bs[kk][n] = W[(k0 + kk) * 128 + bn + n];
        }
        __syncthreads();
#pragma unroll
        for (int kk = 0; kk < 16; kk++) {
            float a[4], b[4];
#pragma unroll
            for (int i = 0; i < 4; i++) a[i] = As[kk][tr * 4 + i];
#pragma unroll
            for (int j = 0; j < 4; j++) b[j] = Bs[kk][tc * 4 + j];
#pragma unroll
            for (int i = 0; i < 4; i++)
#pragma unroll
                for (int j = 0; j < 4; j++) acc[i][j] = fmaf(a[i], b[j], acc[i][j]);
        }
        __syncthreads();
    }
#pragma unroll
    for (int i = 0; i < 4; i++) {
        float4 v = make_float4(acc[i][0], acc[i][1], acc[i][2], acc[i][3]);
        *reinterpret_cast<float4*>(&gH[(bm + tr * 4 + i) * 128 + bn + tc * 4]) = v;
    }
}

// ---------------------------------------------------------------------------
// Kernel 2: fused GAT attention via sorted prefix-sum decomposition.
// One block per (b, head). 256 threads.
//
// For query i with t = s_i, sorted d ascending:
//   branch A (d_j >= -t):  exp(t + d_j)        -> suffix sums of e^{d-dmax}
//   branch B (d_j <  -t):  exp(0.2(t + d_j))   -> prefix sums of e^{0.2(d-dmax)}
// out_i = (w1*V1 + w2*V2) / (w1*S1 + w2*S2)
// ---------------------------------------------------------------------------
__global__ __launch_bounds__(256) void gat_kernel(const float* __restrict__ a_src,
                                                  const float* __restrict__ a_dst,
                                                  float* __restrict__ out) {
    __shared__ float          dv[1024];
    __shared__ unsigned short perm[1024];
    __shared__ float          sS[1024];
    __shared__ float          e1[1024], e2[1024];
    __shared__ float          pe1[1024], pe2[1024];      // segment-local inclusive prefixes
    __shared__ float          segTotS[2][4], segOffS[2][4];
    __shared__ float          segTotV[2][4][32], vecOff[2][4][32];
    __shared__ float          totS[2];
    __shared__ float          totV[2][32];
    __shared__ float          asr[32], ads[32];

    const int bh   = blockIdx.x;
    const int b    = bh >> 2;
    const int head = bh & 3;
    const int tid  = threadIdx.x;

    const float* hbase = gH + (b * 1024) * 128 + head * 32;    // row j: hbase + j*128 + c
    float*       pvg   = gPV + bh * 2 * 1024 * 32;

    if (tid < 32) {
        asr[tid] = a_src[head * 32 + tid];
        ads[tid] = a_dst[head * 32 + tid];
    }
    __syncthreads();

    // --- per-node attention scalars: d_j = h.a_dst, s_i = h.a_src ---
    for (int r = tid; r < 1024; r += 256) {
        const float4* row = reinterpret_cast<const float4*>(hbase + r * 128);
        float accd = 0.f, accs = 0.f;
#pragma unroll
        for (int c4 = 0; c4 < 8; c4++) {
            float4 v = row[c4];
            accd = fmaf(v.x, ads[c4 * 4 + 0], accd);
            accd = fmaf(v.y, ads[c4 * 4 + 1], accd);
            accd = fmaf(v.z, ads[c4 * 4 + 2], accd);
            accd = fmaf(v.w, ads[c4 * 4 + 3], accd);
            accs = fmaf(v.x, asr[c4 * 4 + 0], accs);
            accs = fmaf(v.y, asr[c4 * 4 + 1], accs);
            accs = fmaf(v.z, asr[c4 * 4 + 2], accs);
            accs = fmaf(v.w, asr[c4 * 4 + 3], accs);
        }
        dv[r]   = accd;
        sS[r]   = accs;
        perm[r] = (unsigned short)r;
    }
    __syncthreads();

    // --- bitonic sort of dv ascending, carrying permutation ---
    for (int k = 2; k <= 1024; k <<= 1) {
        for (int j = k >> 1; j > 0; j >>= 1) {
            for (int i = tid; i < 1024; i += 256) {
                int ixj = i ^ j;
                if (ixj > i) {
                    bool  up = ((i & k) == 0);
                    float vi = dv[i], vx = dv[ixj];
                    bool  sw = up ? (vi > vx) : (vi < vx);
                    if (sw) {
                        dv[i] = vx; dv[ixj] = vi;
                        unsigned short p = perm[i]; perm[i] = perm[ixj]; perm[ixj] = p;
                    }
                }
            }
            __syncthreads();
        }
    }

    const float dmax = dv[1023];
    for (int r = tid; r < 1024; r += 256) {
        float x = dv[r] - dmax;           // <= 0
        e1[r] = __expf(x);
        e2[r] = __expf(NEG * x);
    }
    __syncthreads();

    // --- scalar segment-local inclusive prefixes (threads 0..7) ---
    if (tid < 8) {
        int          f  = tid >> 2, seg = tid & 3;
        const float* e  = f ? e2 : e1;
        float*       pe = f ? pe2 : pe1;
        float        acc  = 0.f;
        int          base = seg * 256;
        for (int j = 0; j < 256; j++) { acc += e[base + j]; pe[base + j] = acc; }
        segTotS[f][seg] = acc;
    }
    // --- vector segment-local inclusive prefixes (all 256 threads) ---
    {
        int          seg  = tid >> 6;       // 0..3
        int          chan = tid & 63;       // family*32 + c
        int          f    = chan >> 5;
        int          c    = chan & 31;
        const float* e    = f ? e2 : e1;
        float*       pv   = pvg + f * 1024 * 32;
        float        acc  = 0.f;
        int          base = seg * 256;
        for (int j = base; j < base + 256; j++) {
            int src = perm[j];
            acc = fmaf(e[j], hbase[src * 128 + c], acc);
            pv[j * 32 + c] = acc;
        }
        segTotV[f][seg][c] = acc;
    }
    __syncthreads();

    if (tid < 2) {
        float o = 0.f;
#pragma unroll
        for (int s = 0; s < 4; s++) { segOffS[tid][s] = o; o += segTotS[tid][s]; }
        totS[tid] = o;
    }
    if (tid < 64) {
        int   f = tid >> 5, c = tid & 31;
        float o = 0.f;
#pragma unroll
        for (int s = 0; s < 4; s++) { vecOff[f][s][c] = o; o += segTotV[f][s][c]; }
        totV[f][c] = o;
    }
    __syncthreads();

    // --- queries: warp per query, lane per output channel ---
    const int    lane = tid & 31, wrp = tid >> 5;
    const float  T1   = totS[0];
    const float* pv1  = pvg;
    const float* pv2  = pvg + 1024 * 32;

    for (int i = wrp; i < 1024; i += 8) {
        float t   = sS[i];
        float key = -t;
        // lower_bound: k = #{ d_j < -t }  (branchless binary search, uniform per warp)
        int k = 0;
#pragma unroll
        for (int step = 1024; step >= 1; step >>= 1) {
            int nk = k + step;
            if (nk <= 1024 && dv[nk - 1] < key) k = nk;
        }
        float u  = t + dmax;
        float m  = fmaxf(u, NEG * u);
        float w1 = __expf(u - m);
        float w2 = __expf(NEG * u - m);

        float P1 = 0.f, P2 = 0.f, q1 = 0.f, q2 = 0.f;
        if (k > 0) {
            int km = k - 1, seg = km >> 8;
            P1 = pe1[km] + segOffS[0][seg];
            P2 = pe2[km] + segOffS[1][seg];
            q1 = pv1[km * 32 + lane] + vecOff[0][seg][lane];
            q2 = pv2[km * 32 + lane] + vecOff[1][seg][lane];
        }
        float S1  = T1 - P1;             // suffix scalar, branch A
        float den = fmaf(w1, S1, w2 * P2);
        float inv = 1.f / den;
        float V1  = totV[0][lane] - q1;  // suffix vector, branch A
        float ov  = fmaf(w1, V1, w2 * q2) * inv;
        out[(b * 1024 + i) * 128 + head * 32 + lane] = ov;
    }
}

// ---------------------------------------------------------------------------
extern "C" void kernel_launch(void* const* d_in, const int* in_sizes, int n_in,
                              void* d_out, int out_size) {
    const float* x     = (const float*)d_in[0];
    const float* W     = (const float*)d_in[1];
    const float* a_src = (const float*)d_in[2];
    const float* a_dst = (const float*)d_in[3];
    float*       out   = (float*)d_out;

    dim3 g(B_ * N_ / 64, OUTF_ / 64);
    gemm_kernel<<<g, 256>>>(x, W);
    gat_kernel<<<B_ * H_, 256>>>(a_src, a_dst, out);
}

// round 3
// speedup vs baseline: 3.3248x; 3.3248x over previous
#include <cuda_runtime.h>

#define B_    8
#define N_    1024
#define H_    4
#define NEG   0.2f
#define BH_   (B_ * H_)

// Scratch (__device__ globals; no allocation allowed)
__device__ float          gH[B_ * N_ * 128];          // projected features (4 MB)
__device__ float          gSS[BH_ * N_];              // s_i, original order
__device__ int            gKK[BH_ * N_];              // split index per query
__device__ float          gE1[BH_ * N_], gE2[BH_ * N_];   // exp terms, sorted order
__device__ float          gPE1[BH_ * N_], gPE2[BH_ * N_]; // full inclusive scalar prefixes
__device__ unsigned short gPerm[BH_ * N_];
__device__ float          gDmax[BH_];
__device__ float          gPV[2 * BH_ * N_ * 32];     // full inclusive vector prefixes (8.4 MB)

// ---------------------------------------------------------------------------
// Kernel 1: h = x @ W   (8192x128 @ 128x128, fp32). 64x64 tile, 4x4/thread.
// ---------------------------------------------------------------------------
__global__ __launch_bounds__(256) void gemm_kernel(const float* __restrict__ A,
                                                   const float* __restrict__ W) {
    __shared__ float As[16][64];
    __shared__ float Bs[16][64];
    const int bm = blockIdx.x * 64, bn = blockIdx.y * 64;
    const int tid = threadIdx.x, tr = tid >> 4, tc = tid & 15;

    float acc[4][4];
#pragma unroll
    for (int i = 0; i < 4; i++)
#pragma unroll
        for (int j = 0; j < 4; j++) acc[i][j] = 0.f;

    for (int k0 = 0; k0 < 128; k0 += 16) {
#pragma unroll 4
        for (int i = tid; i < 1024; i += 256) {
            int m = i >> 4, kk = i & 15;
            As[kk][m] = A[(bm + m) * 128 + k0 + kk];
        }
#pragma unroll 4
        for (int i = tid; i < 1024; i += 256) {
            int kk = i >> 6, n = i & 63;
            Bs[kk][n] = W[(k0 + kk) * 128 + bn + n];
        }
        __syncthreads();
#pragma unroll
        for (int kk = 0; kk < 16; kk++) {
            float a[4], b[4];
#pragma unroll
            for (int i = 0; i < 4; i++) a[i] = As[kk][tr * 4 + i];
#pragma unroll
            for (int j = 0; j < 4; j++) b[j] = Bs[kk][tc * 4 + j];
#pragma unroll
            for (int i = 0; i < 4; i++)
#pragma unroll
                for (int j = 0; j < 4; j++) acc[i][j] = fmaf(a[i], b[j], acc[i][j]);
        }
        __syncthreads();
    }
#pragma unroll
    for (int i = 0; i < 4; i++)
        *reinterpret_cast<float4*>(&gH[(bm + tr * 4 + i) * 128 + bn + tc * 4]) =
            make_float4(acc[i][0], acc[i][1], acc[i][2], acc[i][3]);
}

// ---------------------------------------------------------------------------
// Kernel 2: per-(b,h) prep. 1024 threads, one element/query per thread.
// dots -> bitonic sort(d, perm) -> exp -> block scan (pe1, pe2) ->
// parallel binary search for k_i.
// ---------------------------------------------------------------------------
__global__ __launch_bounds__(1024) void prep_kernel(const float* __restrict__ a_src,
                                                    const float* __restrict__ a_dst) {
    __shared__ float          dv[1024];
    __shared__ unsigned short pm[1024];
    __shared__ float          wsum[32];
    __shared__ float          asr[32], ads[32];

    const int bh = blockIdx.x, b = bh >> 2, head = bh & 3;
    const int tid = threadIdx.x, lane = tid & 31, wid = tid >> 5;
    const float* hbase = gH + (b * 1024) * 128 + head * 32;

    if (tid < 32) { asr[tid] = a_src[head * 32 + tid]; ads[tid] = a_dst[head * 32 + tid]; }
    __syncthreads();

    // dot products
    float s;
    {
        const float4* row = reinterpret_cast<const float4*>(hbase + tid * 128);
        float accd = 0.f, accs = 0.f;
#pragma unroll
        for (int c4 = 0; c4 < 8; c4++) {
            float4 v = row[c4];
            accd = fmaf(v.x, ads[c4*4+0], accd); accd = fmaf(v.y, ads[c4*4+1], accd);
            accd = fmaf(v.z, ads[c4*4+2], accd); accd = fmaf(v.w, ads[c4*4+3], accd);
            accs = fmaf(v.x, asr[c4*4+0], accs); accs = fmaf(v.y, asr[c4*4+1], accs);
            accs = fmaf(v.z, asr[c4*4+2], accs); accs = fmaf(v.w, asr[c4*4+3], accs);
        }
        dv[tid] = accd; pm[tid] = (unsigned short)tid; s = accs;
        gSS[bh * 1024 + tid] = accs;
    }
    __syncthreads();

    // bitonic sort ascending (1 element/thread; partner touched by one thread only)
    for (int k = 2; k <= 1024; k <<= 1) {
        for (int j = k >> 1; j > 0; j >>= 1) {
            int ixj = tid ^ j;
            if (ixj > tid) {
                bool  up = ((tid & k) == 0);
                float vi = dv[tid], vx = dv[ixj];
                if (up ? (vi > vx) : (vi < vx)) {
                    dv[tid] = vx; dv[ixj] = vi;
                    unsigned short p = pm[tid]; pm[tid] = pm[ixj]; pm[ixj] = p;
                }
            }
            __syncthreads();
        }
    }

    const float dmax = dv[1023];
    if (tid == 0) gDmax[bh] = dmax;

    float x  = dv[tid] - dmax;
    float e1 = __expf(x);
    float e2 = __expf(NEG * x);
    gE1[bh * 1024 + tid]   = e1;
    gE2[bh * 1024 + tid]   = e2;
    gPerm[bh * 1024 + tid] = pm[tid];

    // inclusive block scans of e1, e2
#pragma unroll
    for (int f = 0; f < 2; f++) {
        float v = f ? e2 : e1;
#pragma unroll
        for (int off = 1; off < 32; off <<= 1) {
            float n = __shfl_up_sync(0xFFFFFFFFu, v, off);
            if (lane >= off) v += n;
        }
        if (lane == 31) wsum[wid] = v;
        __syncthreads();
        if (wid == 0) {
            float w = wsum[lane];
#pragma unroll
            for (int off = 1; off < 32; off <<= 1) {
                float n = __shfl_up_sync(0xFFFFFFFFu, w, off);
                if (lane >= off) w += n;
            }
            wsum[lane] = w;
        }
        __syncthreads();
        float tot = v + (wid ? wsum[wid - 1] : 0.f);
        (f ? gPE2 : gPE1)[bh * 1024 + tid] = tot;
        __syncthreads();
    }

    // parallel binary search: k = #{ d_j < -s_i }  (dv still holds sorted d)
    {
        float key = -s;
        int   k   = 0;
#pragma unroll
        for (int step = 1024; step >= 1; step >>= 1) {
            int nk = k + step;
            if (nk <= 1024 && dv[nk - 1] < key) k = nk;
        }
        gKK[bh * 1024 + tid] = k;
    }
}

// ---------------------------------------------------------------------------
// Kernel 3: vector inclusive prefixes. Block = (bh, family). 1024 threads:
// 32 segments x 32 channels. Two-pass: totals -> offsets -> baked prefixes.
// ---------------------------------------------------------------------------
__global__ __launch_bounds__(1024) void pv_kernel() {
    __shared__ float          e[1024];
    __shared__ unsigned short pm[1024];
    __shared__ float          tot[32][32];

    const int bh = blockIdx.x, f = blockIdx.y;
    const int b = bh >> 2, head = bh & 3;
    const int tid = threadIdx.x, seg = tid >> 5, c = tid & 31;
    const float* hbase = gH + (b * 1024) * 128 + head * 32;

    e[tid]  = (f ? gE2 : gE1)[bh * 1024 + tid];
    pm[tid] = gPerm[bh * 1024 + tid];
    __syncthreads();

    const int j0 = seg * 32;
    float acc = 0.f;
#pragma unroll 8
    for (int jj = 0; jj < 32; jj++) {
        int j = j0 + jj;
        acc = fmaf(e[j], hbase[pm[j] * 128 + c], acc);
    }
    tot[seg][c] = acc;
    __syncthreads();

    float off = 0.f;
    for (int sg = 0; sg < seg; sg++) off += tot[sg][c];

    float* dst = gPV + (size_t)(f * BH_ + bh) * 1024 * 32;
    float acc2 = off;
#pragma unroll 8
    for (int jj = 0; jj < 32; jj++) {
        int j = j0 + jj;
        acc2 = fmaf(e[j], hbase[pm[j] * 128 + c], acc2);
        dst[j * 32 + c] = acc2;
    }
}

// ---------------------------------------------------------------------------
// Kernel 4: queries. One warp per query (32768 warps), pure gathers.
// ---------------------------------------------------------------------------
__global__ __launch_bounds__(256) void query_kernel(float* __restrict__ out) {
    const int gw   = (blockIdx.x * 256 + threadIdx.x) >> 5;  // global warp = query id
    const int lane = threadIdx.x & 31;
    const int bh   = gw >> 10, i = gw & 1023;
    const int b    = bh >> 2, head = bh & 3;

    const float* pv1 = gPV + (size_t)bh * 1024 * 32;
    const float* pv2 = gPV + (size_t)(BH_ + bh) * 1024 * 32;

    const float s    = gSS[bh * 1024 + i];
    const int   k    = gKK[bh * 1024 + i];
    const float dmax = gDmax[bh];
    const float T1   = gPE1[bh * 1024 + 1023];
    const float tot1 = pv1[1023 * 32 + lane];

    float u  = s + dmax;
    float m  = fmaxf(u, NEG * u);
    float w1 = __expf(u - m);
    float w2 = __expf(NEG * u - m);

    float P1 = 0.f, P2 = 0.f, q1 = 0.f, q2 = 0.f;
    if (k > 0) {
        int km = k - 1;
        P1 = gPE1[bh * 1024 + km];
        P2 = gPE2[bh * 1024 + km];
        q1 = pv1[km * 32 + lane];
        q2 = pv2[km * 32 + lane];
    }
    float den = fmaf(w1, T1 - P1, w2 * P2);
    float ov  = fmaf(w1, tot1 - q1, w2 * q2) * (1.f / den);
    out[(b * 1024 + i) * 128 + head * 32 + lane] = ov;
}

// ---------------------------------------------------------------------------
extern "C" void kernel_launch(void* const* d_in, const int* in_sizes, int n_in,
                              void* d_out, int out_size) {
    const float* x     = (const float*)d_in[0];
    const float* W     = (const float*)d_in[1];
    const float* a_src = (const float*)d_in[2];
    const float* a_dst = (const float*)d_in[3];
    float*       out   = (float*)d_out;

    gemm_kernel<<<dim3(B_ * N_ / 64, 2), 256>>>(x, W);
    prep_kernel<<<BH_, 1024>>>(a_src, a_dst);
    pv_kernel<<<dim3(BH_, 2), 1024>>>();
    query_kernel<<<BH_ * N_ / 8, 256>>>(out);
}

// round 4
// speedup vs baseline: 3.4525x; 1.0384x over previous
#include <cuda_runtime.h>

#define B_    8
#define N_    1024
#define H_    4
#define NEG   0.2f
#define BH_   (B_ * H_)

// Scratch (__device__ globals; no allocation allowed)
__device__ float gH[B_ * N_ * 128];            // projected features (4 MB)
__device__ float gPV[2 * BH_ * N_ * 32];       // vector inclusive prefixes (8.4 MB)

// ---------------------------------------------------------------------------
// Kernel 1: h = x @ W   (8192x128 @ 128x128, fp32). 64x64 tile, 4x4/thread.
// Near the fp32 FMA pipe floor already.
// ---------------------------------------------------------------------------
__global__ __launch_bounds__(256) void gemm_kernel(const float* __restrict__ A,
                                                   const float* __restrict__ W) {
    __shared__ float As[16][64];
    __shared__ float Bs[16][64];
    const int bm = blockIdx.x * 64, bn = blockIdx.y * 64;
    const int tid = threadIdx.x, tr = tid >> 4, tc = tid & 15;

    float acc[4][4];
#pragma unroll
    for (int i = 0; i < 4; i++)
#pragma unroll
        for (int j = 0; j < 4; j++) acc[i][j] = 0.f;

    for (int k0 = 0; k0 < 128; k0 += 16) {
#pragma unroll 4
        for (int i = tid; i < 1024; i += 256) {
            int m = i >> 4, kk = i & 15;
            As[kk][m] = A[(bm + m) * 128 + k0 + kk];
        }
#pragma unroll 4
        for (int i = tid; i < 1024; i += 256) {
            int kk = i >> 6, n = i & 63;
            Bs[kk][n] = W[(k0 + kk) * 128 + bn + n];
        }
        __syncthreads();
#pragma unroll
        for (int kk = 0; kk < 16; kk++) {
            float a[4], b[4];
#pragma unroll
            for (int i = 0; i < 4; i++) a[i] = As[kk][tr * 4 + i];
#pragma unroll
            for (int j = 0; j < 4; j++) b[j] = Bs[kk][tc * 4 + j];
#pragma unroll
            for (int i = 0; i < 4; i++)
#pragma unroll
                for (int j = 0; j < 4; j++) acc[i][j] = fmaf(a[i], b[j], acc[i][j]);
        }
        __syncthreads();
    }
#pragma unroll
    for (int i = 0; i < 4; i++)
        *reinterpret_cast<float4*>(&gH[(bm + tr * 4 + i) * 128 + bn + tc * 4]) =
            make_float4(acc[i][0], acc[i][1], acc[i][2], acc[i][3]);
}

// ---------------------------------------------------------------------------
// Mega kernel: per-(b,h) block, 1024 threads. Dots -> hybrid shfl/smem
// bitonic sort -> exps -> scalar scans -> binary search + per-query scalars
// -> vector prefixes (smem-resident h slice) -> fused queries.
// ---------------------------------------------------------------------------
struct MegaSmem {
    float          hL[1024 * 33];     // head slice, stride-33 padded (132 KB)
    float          dv[1024];
    float          e1[1024], e2[1024];
    float          pe1[1024], pe2[1024];
    float          c1s[1024], c2s[1024];
    int            kms[1024];
    unsigned short pm[1024];
    float          tot[32][32];
    float          totV[2][32];
    float          wsum[32];
    float          asr[32], ads[32];
};

__device__ __forceinline__ void shfl_pass(float& v, int& idx, int j, int k, int tid) {
    float pv = __shfl_xor_sync(0xFFFFFFFFu, v, j);
    int   pi = __shfl_xor_sync(0xFFFFFFFFu, idx, j);
    bool  up   = ((tid & k) == 0);
    bool  iLow = ((tid & j) == 0);
    float lo = iLow ? v : pv, hi = iLow ? pv : v;
    bool  sw = up ? (lo > hi) : (lo < hi);
    if (sw) { v = pv; idx = pi; }
}

__global__ __launch_bounds__(1024) void mega_kernel(const float* __restrict__ a_src,
                                                    const float* __restrict__ a_dst,
                                                    float* __restrict__ out) {
    extern __shared__ char smem_raw[];
    MegaSmem& S = *reinterpret_cast<MegaSmem*>(smem_raw);

    const int bh = blockIdx.x, b = bh >> 2, head = bh & 3;
    const int tid = threadIdx.x, lane = tid & 31, wid = tid >> 5;
    const float* hbase = gH + (b * 1024) * 128 + head * 32;

    if (tid < 32) { S.asr[tid] = a_src[head * 32 + tid]; S.ads[tid] = a_dst[head * 32 + tid]; }

    // --- load head slice into smem (stride 33, conflict-free) ---
#pragma unroll
    for (int g = tid; g < 32768; g += 1024) {
        int r = g >> 5, c = g & 31;
        S.hL[r * 33 + c] = hbase[r * 128 + c];
    }
    __syncthreads();

    // --- dots ---
    float v, s;
    {
        float accd = 0.f, accs = 0.f;
#pragma unroll
        for (int c = 0; c < 32; c++) {
            float hv = S.hL[tid * 33 + c];
            accd = fmaf(hv, S.ads[c], accd);
            accs = fmaf(hv, S.asr[c], accs);
        }
        v = accd; s = accs;
    }
    int idx = tid;

    // --- bitonic sort: k=2..32 entirely in registers (shfl) ---
#pragma unroll
    for (int k = 2; k <= 32; k <<= 1)
#pragma unroll
        for (int j = k >> 1; j >= 1; j >>= 1) shfl_pass(v, idx, j, k, tid);
    S.dv[tid] = v; S.pm[tid] = (unsigned short)idx;
    __syncthreads();

    // --- k=64..1024: cross-warp passes in smem, tail passes via shfl ---
    for (int k = 64; k <= 1024; k <<= 1) {
        for (int j = k >> 1; j >= 32; j >>= 1) {
            float          v0 = S.dv[tid];
            unsigned short i0 = S.pm[tid];
            float          pv = S.dv[tid ^ j];
            unsigned short pi = S.pm[tid ^ j];
            bool  up   = ((tid & k) == 0);
            bool  iLow = ((tid & j) == 0);
            float lo = iLow ? v0 : pv, hi = iLow ? pv : v0;
            bool  sw = up ? (lo > hi) : (lo < hi);
            __syncthreads();
            S.dv[tid] = sw ? pv : v0;
            S.pm[tid] = sw ? pi : i0;
            __syncthreads();
        }
        v = S.dv[tid]; idx = S.pm[tid];
#pragma unroll
        for (int j = 16; j >= 1; j >>= 1) shfl_pass(v, idx, j, k, tid);
        S.dv[tid] = v; S.pm[tid] = (unsigned short)idx;
        __syncthreads();
    }

    // --- exps (v == sorted d at tid) ---
    const float dmax = S.dv[1023];
    float x   = v - dmax;
    float e1v = __expf(x);
    float e2v = __expf(NEG * x);
    S.e1[tid] = e1v;
    S.e2[tid] = e2v;

    // --- inclusive block scans of e1, e2 ---
#pragma unroll
    for (int f = 0; f < 2; f++) {
        float sv = f ? e2v : e1v;
#pragma unroll
        for (int off = 1; off < 32; off <<= 1) {
            float n = __shfl_up_sync(0xFFFFFFFFu, sv, off);
            if (lane >= off) sv += n;
        }
        if (lane == 31) S.wsum[wid] = sv;
        __syncthreads();
        if (wid == 0) {
            float w = S.wsum[lane];
#pragma unroll
            for (int off = 1; off < 32; off <<= 1) {
                float n = __shfl_up_sync(0xFFFFFFFFu, w, off);
                if (lane >= off) w += n;
            }
            S.wsum[lane] = w;
        }
        __syncthreads();
        (f ? S.pe2 : S.pe1)[tid] = sv + (wid ? S.wsum[wid - 1] : 0.f);
        __syncthreads();
    }

    // --- binary search + per-query scalars (thread = query) ---
    {
        const float T1 = S.pe1[1023];
        float key = -s;
        int   k   = 0;
#pragma unroll
        for (int step = 1024; step >= 1; step >>= 1) {
            int nk = k + step;
            if (nk <= 1024 && S.dv[nk - 1] < key) k = nk;
        }
        int   km = k - 1;
        float u  = s + dmax;
        float m  = fmaxf(u, NEG * u);
        float w1 = __expf(u - m);
        float w2 = __expf(NEG * u - m);
        float P1 = (k > 0) ? S.pe1[km] : 0.f;
        float P2 = (k > 0) ? S.pe2[km] : 0.f;
        float den = fmaf(w1, T1 - P1, w2 * P2);
        float inv = 1.f / den;
        S.c1s[tid] = w1 * inv;
        S.c2s[tid] = w2 * inv;
        S.kms[tid] = km;
    }

    // --- vector inclusive prefixes from smem h slice; write to gPV ---
#pragma unroll
    for (int f = 0; f < 2; f++) {
        const float* e   = f ? S.e2 : S.e1;
        float*       dst = gPV + (size_t)(f * BH_ + bh) * 32768;
        const int    seg = wid, c = lane, j0 = seg * 32;
        float acc = 0.f;
#pragma unroll
        for (int jj = 0; jj < 32; jj++) {
            int j = j0 + jj;
            acc = fmaf(e[j], S.hL[S.pm[j] * 33 + c], acc);
        }
        S.tot[seg][c] = acc;
        __syncthreads();
        float off = 0.f;
        for (int sg = 0; sg < seg; sg++) off += S.tot[sg][c];
        acc = off;
#pragma unroll
        for (int jj = 0; jj < 32; jj++) {
            int j = j0 + jj;
            acc = fmaf(e[j], S.hL[S.pm[j] * 33 + c], acc);
            dst[j * 32 + c] = acc;
        }
        if (seg == 31) S.totV[f][c] = acc;
        __syncthreads();
    }

    // --- make gPV writes visible to whole block, then fused queries ---
    __threadfence();
    __syncthreads();

    const float* pv1 = gPV + (size_t)bh * 32768;
    const float* pv2 = gPV + (size_t)(BH_ + bh) * 32768;
    const float  tv1 = S.totV[0][lane];
    float* obase = out + (size_t)(b * 1024) * 128 + head * 32 + lane;

#pragma unroll 4
    for (int q = 0; q < 32; q++) {
        int   i  = wid * 32 + q;
        int   km = S.kms[i];
        float c1 = S.c1s[i], c2 = S.c2s[i];
        float q1 = 0.f, q2 = 0.f;
        if (km >= 0) {
            q1 = pv1[km * 32 + lane];
            q2 = pv2[km * 32 + lane];
        }
        obase[(size_t)i * 128] = fmaf(c1, tv1 - q1, c2 * q2);
    }
}

// ---------------------------------------------------------------------------
extern "C" void kernel_launch(void* const* d_in, const int* in_sizes, int n_in,
                              void* d_out, int out_size) {
    const float* x     = (const float*)d_in[0];
    const float* W     = (const float*)d_in[1];
    const float* a_src = (const float*)d_in[2];
    const float* a_dst = (const float*)d_in[3];
    float*       out   = (float*)d_out;

    static int smem_set = 0;
    if (!smem_set) {
        cudaFuncSetAttribute(mega_kernel, cudaFuncAttributeMaxDynamicSharedMemorySize,
                             (int)sizeof(MegaSmem));
        smem_set = 1;
    }

    gemm_kernel<<<dim3(B_ * N_ / 64, 2), 256>>>(x, W);
    mega_kernel<<<BH_, 1024, sizeof(MegaSmem)>>>(a_src, a_dst, out);
}